// round 12
// baseline (speedup 1.0000x reference)
#include <cuda_runtime.h>
#include <cuda_bf16.h>
#include <cstdint>

// LinearMPC via mma.sync bf16 split hi/lo, cluster-of-8 u-exchange.
// u <- clip(u - s*(uH + f)), 100 iters, B=2048, M=512, H symmetric.
// R12: H resident in SMEM (bf16 hi/lo, ldmatrix B-frags);
//      u packed words in gmem, A-frags via direct LDG.cg -> regs (PRMT decode);
//      no cp.async, no k-loop barriers, 1 cluster_sync per iteration.

#define MD 512
#define BATCH 2048
#define ITERS 100
#define STEPC 0.01f
#define CLS 8
#define CB 128            // batch rows per cluster
#define NC 64             // output cols per CTA
#define THREADS 256
#define HSTR 1040u        // H smem row stride bytes (1024 + 16)
#define SM_HL 66560u      // lo plane offset = 64*HSTR
#define SM_F  133120u     // f slice offset
#define FSTR 72u          // f smem row stride (floats)
#define SMEM_TOTAL 169984 // SM_F + 128*FSTR*4

__device__ __align__(16) float    g_f [BATCH * MD];
__device__ __align__(16) uint32_t g_up[BATCH * MD];   // (bf16hi<<16)|bf16lo

__device__ __forceinline__ uint32_t smem_u32_of(const void* p) {
    uint32_t a;
    asm("{ .reg .u64 t; cvta.to.shared.u64 t, %1; cvt.u32.u64 %0, t; }"
        : "=r"(a) : "l"(p));
    return a;
}
__device__ __forceinline__ void ldm_x4(uint32_t* r, uint32_t addr) {
    asm volatile(
        "ldmatrix.sync.aligned.m8n8.x4.shared.b16 {%0,%1,%2,%3}, [%4];"
        : "=r"(r[0]), "=r"(r[1]), "=r"(r[2]), "=r"(r[3]) : "r"(addr));
}
__device__ __forceinline__ void cluster_sync() {
    asm volatile("barrier.cluster.arrive.aligned;" ::: "memory");  // release
    asm volatile("barrier.cluster.wait.aligned;" ::: "memory");    // acquire
}
__device__ __forceinline__ uint32_t prmt(uint32_t a, uint32_t b, uint32_t s) {
    uint32_t d;
    asm("prmt.b32 %0, %1, %2, %3;" : "=r"(d) : "r"(a), "r"(b), "r"(s));
    return d;
}
__device__ __forceinline__ void mma4(float* d, const uint32_t* a,
                                     const uint32_t* b) {
    asm volatile(
        "mma.sync.aligned.m16n8k16.row.col.f32.bf16.bf16.f32 "
        "{%0,%1,%2,%3}, {%4,%5,%6,%7}, {%8,%9}, {%0,%1,%2,%3};"
        : "+f"(d[0]), "+f"(d[1]), "+f"(d[2]), "+f"(d[3])
        : "r"(a[0]), "r"(a[1]), "r"(a[2]), "r"(a[3]), "r"(b[0]), "r"(b[1]));
}
__device__ __forceinline__ float clamp1(float x) {
    return fminf(fmaxf(x, -1.0f), 1.0f);
}
__device__ __forceinline__ uint32_t bfsplit_hi(float x, float& r) {
    __nv_bfloat16 h = __float2bfloat16(x);
    r = x - __bfloat162float(h);
    return (uint32_t)__bfloat16_as_ushort(h);
}
__device__ __forceinline__ uint32_t pack_u(float v) {
    __nv_bfloat16 h = __float2bfloat16(v);
    __nv_bfloat16 l = __float2bfloat16(v - __bfloat162float(h));
    return ((uint32_t)__bfloat16_as_ushort(h) << 16)
         | (uint32_t)__bfloat16_as_ushort(l);
}

// Prologue: f[b, k*8+i] = -2 * Phi[k] @ Q @ (xref[b,k] - xref[b,0])
__global__ void mpc_f_kernel(const float* __restrict__ xref,
                             const float* __restrict__ Phi,
                             const float* __restrict__ Q) {
    int b = blockIdx.x * 4 + threadIdx.y;
    int k = threadIdx.x;
    const float* xr = xref + (size_t)b * 65 * 8;
    float dx[8], t[8];
#pragma unroll
    for (int l = 0; l < 8; l++) dx[l] = xr[k * 8 + l] - xr[l];
#pragma unroll
    for (int j = 0; j < 8; j++) {
        float s = 0.f;
#pragma unroll
        for (int l = 0; l < 8; l++) s = fmaf(Q[j * 8 + l], dx[l], s);
        t[j] = s;
    }
    const float* Pk = Phi + (size_t)k * 64;
#pragma unroll
    for (int i = 0; i < 8; i++) {
        float s = 0.f;
#pragma unroll
        for (int j = 0; j < 8; j++) s = fmaf(Pk[i * 8 + j], t[j], s);
        g_f[(size_t)b * MD + k * 8 + i] = -2.0f * s;
    }
}

// A-chunk (k16) load: 8 LDG.64 into BUF[mf][{(qr,k0),(qr+8,k0),(qr,k8),(qr+8,k8)}]
#define LDA(BUF, KC_) {                                                       \
    const uint2* p_ = up2 + (uint32_t)(KC_) * 8u;                             \
    BUF[0][0] = __ldcg(p_);                                                   \
    BUF[0][1] = __ldcg(p_ + 2048);                                            \
    BUF[0][2] = __ldcg(p_ + 4);                                               \
    BUF[0][3] = __ldcg(p_ + 2052);                                            \
    BUF[1][0] = __ldcg(p_ + 4096);                                            \
    BUF[1][1] = __ldcg(p_ + 6144);                                            \
    BUF[1][2] = __ldcg(p_ + 4100);                                            \
    BUF[1][3] = __ldcg(p_ + 6148);                                            \
}

// One k16 chunk: decode A regs, ldmatrix B hi/lo from SMEM, 24 MMAs.
#define COMPUTE(BUF, KC_) {                                                   \
    uint32_t bh[2][4], bl[2][4];                                              \
    ldm_x4(bh[0], bB0 + (uint32_t)(KC_) * 32u);                               \
    ldm_x4(bh[1], bB1 + (uint32_t)(KC_) * 32u);                               \
    ldm_x4(bl[0], bB0 + SM_HL + (uint32_t)(KC_) * 32u);                       \
    ldm_x4(bl[1], bB1 + SM_HL + (uint32_t)(KC_) * 32u);                       \
    _Pragma("unroll")                                                         \
    for (int mf_ = 0; mf_ < 2; mf_++) {                                       \
        uint32_t ah[4], al[4];                                                \
        _Pragma("unroll")                                                     \
        for (int q_ = 0; q_ < 4; q_++) {                                      \
            ah[q_] = prmt(BUF[mf_][q_].x, BUF[mf_][q_].y, 0x7632u);           \
            al[q_] = prmt(BUF[mf_][q_].x, BUF[mf_][q_].y, 0x5410u);           \
        }                                                                     \
        _Pragma("unroll")                                                     \
        for (int nf_ = 0; nf_ < 4; nf_++) {                                   \
            const uint32_t* Bh = &bh[nf_ >> 1][(nf_ & 1) * 2];                \
            const uint32_t* Bl = &bl[nf_ >> 1][(nf_ & 1) * 2];                \
            float* d_ = acc[mf_][nf_];                                        \
            mma4(d_, ah, Bh);                                                 \
            mma4(d_, al, Bh);                                                 \
            mma4(d_, ah, Bl);                                                 \
        }                                                                     \
    }                                                                         \
}

__global__ void __launch_bounds__(THREADS, 1)
mpc_mma_kernel(const float* __restrict__ Hm, float* __restrict__ out) {
    extern __shared__ char smem[];
    const uint32_t sb = smem_u32_of(smem);
    const int tid = threadIdx.x, lane = tid & 31;
    const int qr = lane >> 2, qc = lane & 3;
    const int w = tid >> 5, wm = w & 3, wn = w >> 2;   // 4 m-groups x 2 n-groups
    uint32_t rank;
    asm("mov.u32 %0, %%cluster_ctarank;" : "=r"(rank));
    const int cb = (int)(blockIdx.x / CLS) * CB;
    const int n0 = (int)rank * NC;

    // ---- Stage H rows [n0, n0+64) as bf16 hi/lo planes (resident forever).
    for (int i = tid * 4; i < NC * MD; i += THREADS * 4) {
        int n = i >> 9, k = i & (MD - 1);
        float4 h = *(const float4*)&Hm[(size_t)(n0 + n) * MD + k];
        float r0, r1, r2, r3, z;
        uint32_t h0 = bfsplit_hi(h.x, r0), h1 = bfsplit_hi(h.y, r1);
        uint32_t h2 = bfsplit_hi(h.z, r2), h3 = bfsplit_hi(h.w, r3);
        uint32_t l0 = bfsplit_hi(r0, z), l1 = bfsplit_hi(r1, z);
        uint32_t l2 = bfsplit_hi(r2, z), l3 = bfsplit_hi(r3, z);
        uint32_t off = (uint32_t)n * HSTR + (uint32_t)(k << 1);
        *(uint2*)(smem + off) = make_uint2(h0 | (h1 << 16), h2 | (h3 << 16));
        *(uint2*)(smem + SM_HL + off) = make_uint2(l0 | (l1 << 16), l2 | (l3 << 16));
    }
    // ---- Stage f slice [128 rows x 64 cols] into padded SMEM.
    for (int i = tid; i < CB * NC; i += THREADS) {
        int r = i >> 6, c = i & 63;
        *(float*)(smem + SM_F + ((uint32_t)r * FSTR + c) * 4u) =
            g_f[(size_t)(cb + r) * MD + n0 + c];
    }

    // ---- Per-lane constants.
    const int lm0 = 32 * wm + qr;              // CTA-local A/out row base
    const int lc0 = 32 * wn + 2 * qc;          // CTA-local out col base
    const uint2* up2 = (const uint2*)g_up + ((uint32_t)(cb + lm0) * 256u + qc);
    const uint32_t bB0 = sb + (uint32_t)(32 * wn + 8 * (lane >> 4) + (lane & 7)) * HSTR
                         + 16u * ((lane >> 3) & 1);
    const uint32_t bB1 = bB0 + 16u * HSTR;

    __syncthreads();

    // ---- Iteration 0: u1 = clip(-s*f) from SMEM f; keep master in regs.
    float u_m[2][4][4];
#pragma unroll
    for (int mf = 0; mf < 2; mf++) {
        uint32_t fr = SM_F + (uint32_t)(lm0 + 16 * mf) * (FSTR * 4u) + lc0 * 4u;
#pragma unroll
        for (int nf = 0; nf < 4; nf++) {
            float2 a = *(const float2*)(smem + fr + 32u * nf);
            float2 b = *(const float2*)(smem + fr + 32u * nf + 8u * FSTR * 4u);
            u_m[mf][nf][0] = clamp1(-STEPC * a.x);
            u_m[mf][nf][1] = clamp1(-STEPC * a.y);
            u_m[mf][nf][2] = clamp1(-STEPC * b.x);
            u_m[mf][nf][3] = clamp1(-STEPC * b.y);
            uint32_t wi = (uint32_t)(cb + lm0 + 16 * mf) * 512u + n0 + lc0 + 8 * nf;
            __stcg((uint2*)(g_up + wi),
                   make_uint2(pack_u(u_m[mf][nf][0]), pack_u(u_m[mf][nf][1])));
            __stcg((uint2*)(g_up + wi + 8u * 512u),
                   make_uint2(pack_u(u_m[mf][nf][2]), pack_u(u_m[mf][nf][3])));
        }
    }

    for (int it = 1; it < ITERS; it++) {
        cluster_sync();   // all cluster CTAs' u stores visible (release/acquire)

        // acc = f (from SMEM).
        float acc[2][4][4];
#pragma unroll
        for (int mf = 0; mf < 2; mf++) {
            uint32_t fr = SM_F + (uint32_t)(lm0 + 16 * mf) * (FSTR * 4u) + lc0 * 4u;
#pragma unroll
            for (int nf = 0; nf < 4; nf++) {
                float2 a = *(const float2*)(smem + fr + 32u * nf);
                float2 b = *(const float2*)(smem + fr + 32u * nf + 8u * FSTR * 4u);
                acc[mf][nf][0] = a.x; acc[mf][nf][1] = a.y;
                acc[mf][nf][2] = b.x; acc[mf][nf][3] = b.y;
            }
        }

        uint2 A4[4][2][4];
        LDA(A4[0], 0);
        LDA(A4[1], 1);
#pragma unroll 1
        for (int kc = 0; kc < 32; kc += 4) {
#pragma unroll
            for (int j = 0; j < 4; j++) {
                int c = kc + j;
                if (c + 2 < 32) LDA(A4[(c + 2) & 3], c + 2);
                COMPUTE(A4[c & 3], c);
            }
        }

        // ---- u <- clip(u - s*acc); store packed words (fp32 out on last).
        const bool last = (it == ITERS - 1);
#pragma unroll
        for (int mf = 0; mf < 2; mf++) {
#pragma unroll
            for (int nf = 0; nf < 4; nf++) {
#pragma unroll
                for (int c = 0; c < 4; c++)
                    u_m[mf][nf][c] =
                        clamp1(fmaf(-STEPC, acc[mf][nf][c], u_m[mf][nf][c]));
                uint32_t wi = (uint32_t)(cb + lm0 + 16 * mf) * 512u
                              + n0 + lc0 + 8 * nf;
                if (last) {
                    *(float2*)&out[wi] = make_float2(u_m[mf][nf][0], u_m[mf][nf][1]);
                    *(float2*)&out[wi + 8u * 512u] =
                        make_float2(u_m[mf][nf][2], u_m[mf][nf][3]);
                } else {
                    __stcg((uint2*)(g_up + wi),
                           make_uint2(pack_u(u_m[mf][nf][0]), pack_u(u_m[mf][nf][1])));
                    __stcg((uint2*)(g_up + wi + 8u * 512u),
                           make_uint2(pack_u(u_m[mf][nf][2]), pack_u(u_m[mf][nf][3])));
                }
            }
        }
    }
}

extern "C" void kernel_launch(void* const* d_in, const int* in_sizes, int n_in,
                              void* d_out, int out_size) {
    // metadata order: x0, xref, H, Phi, Q
    const float* xref = (const float*)d_in[1];
    const float* H    = (const float*)d_in[2];
    const float* Phi  = (const float*)d_in[3];
    const float* Q    = (const float*)d_in[4];
    float* out        = (float*)d_out;

    cudaFuncSetAttribute(mpc_mma_kernel,
                         cudaFuncAttributeMaxDynamicSharedMemorySize, SMEM_TOTAL);

    mpc_f_kernel<<<BATCH / 4, dim3(64, 4, 1)>>>(xref, Phi, Q);

    cudaLaunchConfig_t cfg = {};
    cfg.gridDim = dim3((BATCH / CB) * CLS, 1, 1);   // 128 CTAs, 16 clusters
    cfg.blockDim = dim3(THREADS, 1, 1);
    cfg.dynamicSmemBytes = SMEM_TOTAL;
    cudaLaunchAttribute attrs[1];
    attrs[0].id = cudaLaunchAttributeClusterDimension;
    attrs[0].val.clusterDim.x = CLS;
    attrs[0].val.clusterDim.y = 1;
    attrs[0].val.clusterDim.z = 1;
    cfg.attrs = attrs;
    cfg.numAttrs = 1;
    cudaLaunchKernelEx(&cfg, mpc_mma_kernel, H, out);
}